// round 12
// baseline (speedup 1.0000x reference)
#include <cuda_runtime.h>
#include <cuda_bf16.h>
#include <cstdint>

// Sizes (fixed): B=64, T=1024, D=512, H=256, 4H=1024, two directions.

__device__ float G_buf [(size_t)65536 * 2048];        // [m = b*1024 + t][j]
__device__ float Gt_buf[(size_t)1024 * 2048 * 64];    // [t][j][b]
__device__ float Hhist [(size_t)2 * 1024 * 16384];    // [dir][t][q*64 + b]

// ---------------------------------------------------------------------------
static __device__ __forceinline__ unsigned long long pk2(float x, float y) {
    unsigned long long r;
    asm("mov.b64 %0, {%1, %2};" : "=l"(r) : "f"(x), "f"(y));
    return r;
}
static __device__ __forceinline__ unsigned long long fma2(
    unsigned long long a, unsigned long long b, unsigned long long c) {
    unsigned long long d;
    asm("fma.rn.f32x2 %0, %1, %2, %3;" : "=l"(d) : "l"(a), "l"(b), "l"(c));
    return d;
}
static __device__ __forceinline__ unsigned long long add2(
    unsigned long long a, unsigned long long b) {
    unsigned long long d;
    asm("add.rn.f32x2 %0, %1, %2;" : "=l"(d) : "l"(a), "l"(b));
    return d;
}
static __device__ __forceinline__ float2 upk(unsigned long long v) {
    float2 r;
    asm("mov.b64 {%0, %1}, %2;" : "=f"(r.x), "=f"(r.y) : "l"(v));
    return r;
}
static __device__ __forceinline__ float sigm_f(float x) {
    return __frcp_rn(1.f + __expf(-x));
}
static __device__ __forceinline__ float tanh_f(float x) {
    x = fminf(fmaxf(x, -15.f), 15.f);
    float e = __expf(2.f * x);
    return (e - 1.f) / (e + 1.f);
}
static __device__ __forceinline__ uint32_t smem_u32(const void* p) {
    uint32_t a;
    asm("{ .reg .u64 t; cvta.to.shared.u64 t, %1; cvt.u32.u64 %0, t; }"
        : "=r"(a) : "l"(p));
    return a;
}

// ---------------------------------------------------------------------------
// Phase 1: G[m][j] = x[m,:] . Wih[j,:] + bih[j] + bhh[j]   (proven)
// ---------------------------------------------------------------------------
__global__ void __launch_bounds__(256) gemm_in(
    const float* __restrict__ A,
    const float* __restrict__ Wf, const float* __restrict__ Wb,
    const float* __restrict__ bif, const float* __restrict__ bhf,
    const float* __restrict__ bib, const float* __restrict__ bhb)
{
    __shared__ float As[8][132];
    __shared__ float Bs[8][132];

    const int bn = blockIdx.x;
    const int bm = blockIdx.y;
    const bool fwd = (bn < 8);
    const float* Bm = fwd ? Wf : Wb;
    const int nloc = (bn & 7) * 128;

    const int tid = threadIdx.x;
    const int lr  = tid >> 1;
    const int lk  = (tid & 1) * 4;

    const float* Ap = A  + (size_t)(bm * 128 + lr) * 512 + lk;
    const float* Bp = Bm + (size_t)(nloc + lr) * 512 + lk;

    const int tx = tid & 15;
    const int ty = tid >> 4;

    unsigned long long acc[8][4];
#pragma unroll
    for (int i = 0; i < 8; i++)
#pragma unroll
        for (int j = 0; j < 4; j++) acc[i][j] = 0ull;

    float4 pa = *(const float4*)(Ap);
    float4 pb = *(const float4*)(Bp);

    for (int k0 = 0; k0 < 512; k0 += 8) {
        As[lk + 0][lr] = pa.x; As[lk + 1][lr] = pa.y;
        As[lk + 2][lr] = pa.z; As[lk + 3][lr] = pa.w;
        Bs[lk + 0][lr] = pb.x; Bs[lk + 1][lr] = pb.y;
        Bs[lk + 2][lr] = pb.z; Bs[lk + 3][lr] = pb.w;
        __syncthreads();

        if (k0 + 8 < 512) {
            pa = *(const float4*)(Ap + k0 + 8);
            pb = *(const float4*)(Bp + k0 + 8);
        }

#pragma unroll
        for (int kk = 0; kk < 8; kk++) {
            float4 a0 = *(const float4*)&As[kk][ty * 8];
            float4 a1 = *(const float4*)&As[kk][ty * 8 + 4];
            float4 b0 = *(const float4*)&Bs[kk][tx * 8];
            float4 b1 = *(const float4*)&Bs[kk][tx * 8 + 4];
            unsigned long long bb[4] = {
                pk2(b0.x, b0.y), pk2(b0.z, b0.w),
                pk2(b1.x, b1.y), pk2(b1.z, b1.w)
            };
            float av[8] = {a0.x, a0.y, a0.z, a0.w, a1.x, a1.y, a1.z, a1.w};
#pragma unroll
            for (int i = 0; i < 8; i++) {
                unsigned long long aa = pk2(av[i], av[i]);
#pragma unroll
                for (int j = 0; j < 4; j++)
                    acc[i][j] = fma2(aa, bb[j], acc[i][j]);
            }
        }
        __syncthreads();
    }

    const float* bi = fwd ? bif : bib;
    const float* bh = fwd ? bhf : bhb;
    float bias[8];
#pragma unroll
    for (int j = 0; j < 8; j++) {
        int nl = nloc + tx * 8 + j;
        bias[j] = bi[nl] + bh[nl];
    }
#pragma unroll
    for (int i = 0; i < 8; i++) {
        int m = bm * 128 + ty * 8 + i;
        float* dst = G_buf + (size_t)m * 2048 + bn * 128 + tx * 8;
        float2 c0 = upk(acc[i][0]), c1 = upk(acc[i][1]);
        float2 c2 = upk(acc[i][2]), c3 = upk(acc[i][3]);
        *(float4*)dst       = make_float4(c0.x + bias[0], c0.y + bias[1],
                                          c1.x + bias[2], c1.y + bias[3]);
        *(float4*)(dst + 4) = make_float4(c2.x + bias[4], c2.y + bias[5],
                                          c3.x + bias[6], c3.y + bias[7]);
    }
}

// ---------------------------------------------------------------------------
// Transpose G[b*1024+t][j] -> Gt[t][j][b]   (proven)
// ---------------------------------------------------------------------------
__global__ void __launch_bounds__(256) transp() {
    __shared__ float tile[64][65];
    const int t  = blockIdx.y;
    const int j0 = blockIdx.x * 64;
    const int tid = threadIdx.x;

    const int jq = (tid & 15) * 4;
    const int bb = tid >> 4;
#pragma unroll
    for (int p = 0; p < 4; p++) {
        int bi = bb + p * 16;
        float4 v = *(const float4*)(G_buf + ((size_t)(bi * 1024 + t)) * 2048 + j0 + jq);
        tile[bi][jq + 0] = v.x; tile[bi][jq + 1] = v.y;
        tile[bi][jq + 2] = v.z; tile[bi][jq + 3] = v.w;
    }
    __syncthreads();

    const int bq = (tid & 15) * 4;
    const int jj = tid >> 4;
#pragma unroll
    for (int p = 0; p < 4; p++) {
        int j = jj + p * 16;
        float4 v = make_float4(tile[bq + 0][j], tile[bq + 1][j],
                               tile[bq + 2][j], tile[bq + 3][j]);
        *(float4*)(Gt_buf + ((size_t)t * 2048 + j0 + j) * 64 + bq) = v;
    }
}

// ---------------------------------------------------------------------------
// Phase 2: cluster-based persistent recurrence.
// Cluster = 8 CTAs = one (dir, bgroup-of-8). CTA rank rk owns q in
// [rk*32, rk*32+32) x b in [bg*8, bg*8+8). h exchange: kh0 threads push new
// h directly into ALL 8 CTAs' smem (mapa + st.shared::cluster), double-
// buffered; one barrier.cluster per step. No L2 in the loop.
// FIX vs R11: no peer-push on the final step (peer may exit -> fault), and a
// trailing cluster barrier before exit.
// ---------------------------------------------------------------------------
__global__ void __launch_bounds__(256, 1) __cluster_dims__(8, 1, 1) recur(
    const float* __restrict__ Whf, const float* __restrict__ Whb)
{
    extern __shared__ float sm[];
    float* h_s = sm;                                     // [2][256*8] 16KB
    ulonglong2* w_s = (ulonglong2*)(sm + 4096);          // 32*257 ent  131584B
    unsigned long long* red =
        (unsigned long long*)((char*)sm + 16384 + 131584);  // [8][192] 12KB

    const int cx  = blockIdx.x;
    const int rk  = cx & 7;             // cluster rank = q-slab
    const int cid = cx >> 3;
    const int dir = cid >> 3;
    const int bg  = cid & 7;
    const int b0  = bg * 8;
    const int qb  = rk * 32;            // CTA's q base within direction
    const int tid = threadIdx.x;
    const int b   = tid & 7;
    const int qo  = (tid >> 3) & 7;     // owns q = qb + qo*4 .. +3
    const int kh  = tid >> 6;
    const bool lo = (kh == 0);
    const int lcl = tid & 63;
    const int bglob = b0 + b;

    // Weights: entry index (j*8 + qo)*257 + k  (q_loc = qo*4 + j)
    const float* W = dir ? Whb : Whf;
    for (int idx = tid; idx < 8192; idx += 256) {
        int q_loc = idx >> 8, k = idx & 255;
        int ent = ((q_loc & 3) * 8 + (q_loc >> 2)) * 257 + k;
        int qg  = qb + q_loc;
        ulonglong2 v;
        v.x = pk2(W[(size_t)(      qg) * 256 + k], W[(size_t)(256 + qg) * 256 + k]);
        v.y = pk2(W[(size_t)(512 + qg) * 256 + k], W[(size_t)(768 + qg) * 256 + k]);
        w_s[ent] = v;
    }
    // Zero h buffer 0
    for (int i = tid; i < 2048; i += 256) h_s[i] = 0.f;

    // Peer smem base addresses (all 8 cluster CTAs)
    uint32_t hbase = smem_u32(h_s);
    uint32_t peer[8];
#pragma unroll
    for (int r = 0; r < 8; r++)
        asm("mapa.shared::cluster.u32 %0, %1, %2;" : "=r"(peer[r]) : "r"(hbase), "r"(r));

    float cs[4] = {0.f, 0.f, 0.f, 0.f};

    // Gate prefetch for step 0 (kh0)
    int t = dir ? 1023 : 0;
    float pi[4], pf[4], pg[4], po[4];
    if (lo) {
        const float* gp = Gt_buf + ((size_t)t * 2048 + (size_t)dir * 1024) * 64 + bglob;
#pragma unroll
        for (int j = 0; j < 4; j++) {
            int qg = qb + qo * 4 + j;
            pi[j] = __ldg(gp + (size_t)(      qg) * 64);
            pf[j] = __ldg(gp + (size_t)(256 + qg) * 64);
            pg[j] = __ldg(gp + (size_t)(512 + qg) * 64);
            po[j] = __ldg(gp + (size_t)(768 + qg) * 64);
        }
    }
    __syncthreads();
    asm volatile("barrier.cluster.arrive.aligned;" ::: "memory");
    asm volatile("barrier.cluster.wait.aligned;" ::: "memory");

    float* Hd = Hhist + (size_t)dir * 1024 * 16384;

    for (int step = 0; step < 1024; ++step) {
        const float* hq = h_s + (step & 1) * 2048 + kh * 512 + b;
        const ulonglong2* wq = w_s + qo * 257 + kh * 64;

        unsigned long long aif[4], ago[4];
        if (lo) {
#pragma unroll
            for (int j = 0; j < 4; j++) {
                aif[j] = pk2(pi[j], pf[j]);
                ago[j] = pk2(pg[j], po[j]);
            }
        } else {
#pragma unroll
            for (int j = 0; j < 4; j++) { aif[j] = 0ull; ago[j] = 0ull; }
        }

#pragma unroll 8
        for (int kk = 0; kk < 64; ++kk) {
            float hv = hq[kk * 8];
            unsigned long long hh = pk2(hv, hv);
#pragma unroll
            for (int j = 0; j < 4; j++) {
                ulonglong2 wv = wq[(j * 8) * 257 + kk];
                aif[j] = fma2(hh, wv.x, aif[j]);
                ago[j] = fma2(hh, wv.y, ago[j]);
            }
        }

        if (!lo) {
            int base = (kh - 1) * 64 + lcl;
#pragma unroll
            for (int j = 0; j < 4; j++) {
                red[(2 * j    ) * 192 + base] = aif[j];
                red[(2 * j + 1) * 192 + base] = ago[j];
            }
        }
        __syncthreads();

        if (lo) {
            float hn[4];
#pragma unroll
            for (int j = 0; j < 4; j++) {
#pragma unroll
                for (int g = 0; g < 3; g++) {
                    aif[j] = add2(aif[j], red[(2 * j    ) * 192 + g * 64 + tid]);
                    ago[j] = add2(ago[j], red[(2 * j + 1) * 192 + g * 64 + tid]);
                }
                float2 vif = upk(aif[j]), vgo = upk(ago[j]);
                float ig = sigm_f(vif.x), fg = sigm_f(vif.y);
                float gg = tanh_f(vgo.x), og = sigm_f(vgo.y);
                cs[j] = fg * cs[j] + ig * gg;
                hn[j] = og * tanh_f(cs[j]);
            }
            // Output history (fire-and-forget; consumed only by out_tr)
            float* hd = Hd + (size_t)t * 16384;
#pragma unroll
            for (int j = 0; j < 4; j++)
                __stcg(hd + (qb + qo * 4 + j) * 64 + bglob, hn[j]);
            // Push new h into all 8 cluster CTAs' next-phase buffer.
            // NOT on the last step: a peer may already have exited, and a
            // remote smem store to an exited CTA faults.
            if (step < 1023) {
                uint32_t off = ((step + 1) & 1) * 8192u
                             + (uint32_t)(((qb + qo * 4) * 8 + b) * 4);
#pragma unroll
                for (int r = 0; r < 8; r++) {
                    uint32_t pa = peer[r] + off;
#pragma unroll
                    for (int j = 0; j < 4; j++)
                        asm volatile("st.shared::cluster.f32 [%0], %1;"
                                     :: "r"(pa + j * 32u), "f"(hn[j]) : "memory");
                }
            }
        }

        if (step == 1023) break;

        asm volatile("barrier.cluster.arrive.aligned;" ::: "memory");

        // Hidden under the cluster wait: next step's gate prefetch
        t = dir ? (1022 - step) : (step + 1);
        if (lo) {
            const float* gp = Gt_buf + ((size_t)t * 2048 + (size_t)dir * 1024) * 64 + bglob;
#pragma unroll
            for (int j = 0; j < 4; j++) {
                int qg = qb + qo * 4 + j;
                pi[j] = __ldg(gp + (size_t)(      qg) * 64);
                pf[j] = __ldg(gp + (size_t)(256 + qg) * 64);
                pg[j] = __ldg(gp + (size_t)(512 + qg) * 64);
                po[j] = __ldg(gp + (size_t)(768 + qg) * 64);
            }
        }

        asm volatile("barrier.cluster.wait.aligned;" ::: "memory");
    }

    // Final cluster barrier: no CTA exits while any sibling could still have
    // remote traffic in flight.
    asm volatile("barrier.cluster.arrive.aligned;" ::: "memory");
    asm volatile("barrier.cluster.wait.aligned;" ::: "memory");
}

// ---------------------------------------------------------------------------
// Final: out[b][t][dir*256+q] = Hhist[dir][t][q*64+b]   (proven)
// ---------------------------------------------------------------------------
__global__ void __launch_bounds__(256) out_tr(float* __restrict__ out) {
    __shared__ float tile[64][65];
    const int q0  = blockIdx.x * 64;
    const int t   = blockIdx.y;
    const int dir = blockIdx.z;
    const int tid = threadIdx.x;

    const float* src = Hhist + ((size_t)dir * 1024 + t) * 16384;
    const int b  = tid & 63;
    const int q4 = (tid >> 6) * 16;
#pragma unroll
    for (int i = 0; i < 16; i++) {
        int qq = q4 + i;
        tile[b][qq] = src[(q0 + qq) * 64 + b];
    }
    __syncthreads();

    const int qs = (tid & 15) * 4;
    const int br = tid >> 4;
#pragma unroll
    for (int p = 0; p < 4; p++) {
        int bb = br + p * 16;
        float4 v = make_float4(tile[bb][qs + 0], tile[bb][qs + 1],
                               tile[bb][qs + 2], tile[bb][qs + 3]);
        *(float4*)(out + ((size_t)bb * 1024 + t) * 512 + dir * 256 + q0 + qs) = v;
    }
}

// ---------------------------------------------------------------------------
// Launch
// ---------------------------------------------------------------------------
extern "C" void kernel_launch(void* const* d_in, const int* in_sizes, int n_in,
                              void* d_out, int out_size) {
    const float* x   = (const float*)d_in[0];
    const float* Wif = (const float*)d_in[1];
    const float* Whf = (const float*)d_in[2];
    const float* bif = (const float*)d_in[3];
    const float* bhf = (const float*)d_in[4];
    const float* Wib = (const float*)d_in[5];
    const float* Whb = (const float*)d_in[6];
    const float* bib = (const float*)d_in[7];
    const float* bhb = (const float*)d_in[8];
    float* out = (float*)d_out;

    // 16384 (h double-buffer) + 131584 (w) + 12288 (red) = 160256 bytes
    cudaFuncSetAttribute(recur, cudaFuncAttributeMaxDynamicSharedMemorySize, 160256);

    gemm_in<<<dim3(16, 512), 256>>>(x, Wif, Wib, bif, bhf, bib, bhb);
    transp<<<dim3(32, 1024), 256>>>();
    recur<<<128, 256, 160256>>>(Whf, Whb);
    out_tr<<<dim3(4, 1024, 2), 256>>>(out);
}

// round 14
// speedup vs baseline: 1.6742x; 1.6742x over previous
#include <cuda_runtime.h>
#include <cuda_bf16.h>
#include <cstdint>

// Sizes (fixed): B=64, T=1024, D=512, H=256, 4H=1024, two directions.

__device__ float G_buf [(size_t)65536 * 2048];        // [m = b*1024 + t][j]
__device__ float Gt_buf[(size_t)1024 * 2048 * 64];    // [t][j][b]
__device__ float Hhist [(size_t)2 * 1024 * 16384];    // [dir][t][q*64 + b]
__device__ unsigned g_arrive[2][4][16][32];           // [dir][bgroup][qslice][pad]
__device__ __align__(16) __nv_bfloat16 Abuf[(size_t)65536 * 1536]; // [m][hi|hi|lo]
__device__ __align__(16) __nv_bfloat16 Wbuf[(size_t)2048 * 1536];  // [j][Whi|Wlo|Whi]

// ---------------------------------------------------------------------------
static __device__ __forceinline__ unsigned long long pk2(float x, float y) {
    unsigned long long r;
    asm("mov.b64 %0, {%1, %2};" : "=l"(r) : "f"(x), "f"(y));
    return r;
}
static __device__ __forceinline__ unsigned long long fma2(
    unsigned long long a, unsigned long long b, unsigned long long c) {
    unsigned long long d;
    asm("fma.rn.f32x2 %0, %1, %2, %3;" : "=l"(d) : "l"(a), "l"(b), "l"(c));
    return d;
}
static __device__ __forceinline__ unsigned long long add2(
    unsigned long long a, unsigned long long b) {
    unsigned long long d;
    asm("add.rn.f32x2 %0, %1, %2;" : "=l"(d) : "l"(a), "l"(b));
    return d;
}
static __device__ __forceinline__ float2 upk(unsigned long long v) {
    float2 r;
    asm("mov.b64 {%0, %1}, %2;" : "=f"(r.x), "=f"(r.y) : "l"(v));
    return r;
}
static __device__ __forceinline__ float sigm_f(float x) {
    return __frcp_rn(1.f + __expf(-x));
}
static __device__ __forceinline__ float tanh_f(float x) {
    x = fminf(fmaxf(x, -15.f), 15.f);
    float e = __expf(2.f * x);
    return (e - 1.f) / (e + 1.f);
}
static __device__ __forceinline__ void st_rel(unsigned* p, unsigned v) {
    asm volatile("st.release.gpu.u32 [%0], %1;" :: "l"(p), "r"(v) : "memory");
}
static __device__ __forceinline__ unsigned ld_acq(const unsigned* p) {
    unsigned v;
    asm volatile("ld.acquire.gpu.u32 %0, [%1];" : "=r"(v) : "l"(p) : "memory");
    return v;
}
static __device__ __forceinline__ void cp16(void* smem_dst, const void* gsrc) {
    unsigned s = (unsigned)__cvta_generic_to_shared(smem_dst);
    asm volatile("cp.async.cg.shared.global [%0], [%1], 16;" :: "r"(s), "l"(gsrc));
}

// mma.sync m16n8k16 bf16 (baseline tensor ISA; compiles for compute_103)
static __device__ __forceinline__ void mma_bf16(
    float& c0, float& c1, float& c2, float& c3,
    uint32_t a0, uint32_t a1, uint32_t a2, uint32_t a3,
    uint32_t b0, uint32_t b1) {
    asm volatile(
        "mma.sync.aligned.m16n8k16.row.col.f32.bf16.bf16.f32 "
        "{%0,%1,%2,%3}, {%4,%5,%6,%7}, {%8,%9}, {%0,%1,%2,%3};"
        : "+f"(c0), "+f"(c1), "+f"(c2), "+f"(c3)
        : "r"(a0), "r"(a1), "r"(a2), "r"(a3), "r"(b0), "r"(b1));
}

// ---------------------------------------------------------------------------
__global__ void reset_k() {
    unsigned i = blockIdx.x * 256u + threadIdx.x;
    if (i < 4096u) (&g_arrive[0][0][0][0])[i] = 0u;
}

// ---------------------------------------------------------------------------
// bf16 split conversions: x -> Abuf = [hi|hi|lo], W -> Wbuf = [Whi|Wlo|Whi]
// ---------------------------------------------------------------------------
__global__ void __launch_bounds__(256) convA(const float* __restrict__ x) {
    const int row = blockIdx.x;
    const int t   = threadIdx.x;
    float2 v = *(const float2*)(x + (size_t)row * 512 + t * 2);
    __nv_bfloat16 h0 = __float2bfloat16(v.x);
    __nv_bfloat16 h1 = __float2bfloat16(v.y);
    __nv_bfloat16 l0 = __float2bfloat16(v.x - __bfloat162float(h0));
    __nv_bfloat16 l1 = __float2bfloat16(v.y - __bfloat162float(h1));
    __nv_bfloat162 hh; hh.x = h0; hh.y = h1;
    __nv_bfloat162 ll; ll.x = l0; ll.y = l1;
    __nv_bfloat162* dst = (__nv_bfloat162*)(Abuf + (size_t)row * 1536);
    dst[t] = hh; dst[256 + t] = hh; dst[512 + t] = ll;
}
__global__ void __launch_bounds__(256) convW(
    const float* __restrict__ Wf, const float* __restrict__ Wb) {
    const int j = blockIdx.x;
    const int t = threadIdx.x;
    const float* src = (j < 1024) ? (Wf + (size_t)j * 512)
                                  : (Wb + (size_t)(j - 1024) * 512);
    float2 v = *(const float2*)(src + t * 2);
    __nv_bfloat16 h0 = __float2bfloat16(v.x);
    __nv_bfloat16 h1 = __float2bfloat16(v.y);
    __nv_bfloat16 l0 = __float2bfloat16(v.x - __bfloat162float(h0));
    __nv_bfloat16 l1 = __float2bfloat16(v.y - __bfloat162float(h1));
    __nv_bfloat162 hh; hh.x = h0; hh.y = h1;
    __nv_bfloat162 ll; ll.x = l0; ll.y = l1;
    __nv_bfloat162* dst = (__nv_bfloat162*)(Wbuf + (size_t)j * 1536);
    dst[t] = hh; dst[256 + t] = ll; dst[512 + t] = hh;
}

// ---------------------------------------------------------------------------
// Tensor-core GEMM: G[m][j] = A'[m,:] . W'[j,:], K'=1536, fp32 accum.
// CTA tile 128x128, 8 warps (2m x 4n), warp tile 64x32.
// K staged in chunks of 64 bf16, double-buffered cp.async.
// smem stride 72 bf16 -> conflict-free direct fragment LDS.
// ---------------------------------------------------------------------------
static constexpr int KS = 72;   // smem k-stride (bf16 units)

__global__ void __launch_bounds__(256, 1) gemm_mma() {
    extern __shared__ __align__(16) __nv_bfloat16 smb[];
    // stage s: A at smb + s*18432, W at smb + 36864 + s*9216... compute sizes:
    // A tile 128*72 = 9216 bf16 ; W tile 128*72 = 9216 bf16 ; per stage 18432
    __nv_bfloat16* As[2] = { smb,          smb + 9216  };
    __nv_bfloat16* Ws[2] = { smb + 18432,  smb + 27648 };
    // total 2*18432 = 36864 bf16 = 73728 bytes

    const int tid = threadIdx.x;
    const int wid = tid >> 5;
    const int lane = tid & 31;
    const int gid = lane >> 2;          // 0..7
    const int tig = lane & 3;           // 0..3
    const int wm = wid >> 2;            // 0..1  (m warp)
    const int wn = wid & 3;             // 0..3  (n warp)
    const int n0 = blockIdx.x * 128;
    const int m0 = blockIdx.y * 128;

    float acc[4][4][4];
#pragma unroll
    for (int i = 0; i < 4; i++)
#pragma unroll
        for (int j = 0; j < 4; j++)
#pragma unroll
            for (int k = 0; k < 4; k++) acc[i][j][k] = 0.f;

    // Stage loader: 128 rows x 64 bf16 (8 x 16B per row) for A and W.
    auto load_stage = [&](int s, int kc) {
        const __nv_bfloat16* Ag = Abuf + (size_t)m0 * 1536 + kc * 64;
        const __nv_bfloat16* Wg = Wbuf + (size_t)n0 * 1536 + kc * 64;
#pragma unroll
        for (int i = 0; i < 4; i++) {
            int idx = tid + i * 256;        // 0..1023
            int row = idx >> 3, seg = idx & 7;
            cp16(As[s] + row * KS + seg * 8, Ag + (size_t)row * 1536 + seg * 8);
            cp16(Ws[s] + row * KS + seg * 8, Wg + (size_t)row * 1536 + seg * 8);
        }
        asm volatile("cp.async.commit_group;");
    };

    load_stage(0, 0);

    for (int kc = 0; kc < 24; ++kc) {
        const int s = kc & 1;
        if (kc + 1 < 24) load_stage(s ^ 1, kc + 1);
        // wait until only the newest group (kc+1) may remain in flight
        if (kc + 1 < 24) asm volatile("cp.async.wait_group 1;" ::: "memory");
        else             asm volatile("cp.async.wait_group 0;" ::: "memory");
        __syncthreads();

        const __nv_bfloat16* Ab = As[s] + (wm * 64 + gid) * KS + tig * 2;
        const __nv_bfloat16* Wb2 = Ws[s] + (wn * 32 + gid) * KS + tig * 2;

#pragma unroll
        for (int kk = 0; kk < 4; ++kk) {
            const int k0 = kk * 16;
            uint32_t a[4][4];
#pragma unroll
            for (int mt = 0; mt < 4; mt++) {
                const __nv_bfloat16* p = Ab + mt * 16 * KS + k0;
                a[mt][0] = *(const uint32_t*)(p);
                a[mt][1] = *(const uint32_t*)(p + 8 * KS);
                a[mt][2] = *(const uint32_t*)(p + 8);
                a[mt][3] = *(const uint32_t*)(p + 8 * KS + 8);
            }
            uint32_t bf[4][2];
#pragma unroll
            for (int nt = 0; nt < 4; nt++) {
                const __nv_bfloat16* p = Wb2 + nt * 8 * KS + k0;
                bf[nt][0] = *(const uint32_t*)(p);
                bf[nt][1] = *(const uint32_t*)(p + 8);
            }
#pragma unroll
            for (int mt = 0; mt < 4; mt++)
#pragma unroll
                for (int nt = 0; nt < 4; nt++)
                    mma_bf16(acc[mt][nt][0], acc[mt][nt][1],
                             acc[mt][nt][2], acc[mt][nt][3],
                             a[mt][0], a[mt][1], a[mt][2], a[mt][3],
                             bf[nt][0], bf[nt][1]);
        }
        __syncthreads();   // stage s free for reuse
    }

    // Epilogue: D[m16][n8] frag -> G_buf. c0,c1 row gid; c2,c3 row gid+8.
#pragma unroll
    for (int mt = 0; mt < 4; mt++) {
        int mrow = m0 + wm * 64 + mt * 16 + gid;
#pragma unroll
        for (int nt = 0; nt < 4; nt++) {
            int ncol = n0 + wn * 32 + nt * 8 + tig * 2;
            float* d0 = G_buf + (size_t)mrow * 2048 + ncol;
            float* d1 = G_buf + (size_t)(mrow + 8) * 2048 + ncol;
            *(float2*)d0 = make_float2(acc[mt][nt][0], acc[mt][nt][1]);
            *(float2*)d1 = make_float2(acc[mt][nt][2], acc[mt][nt][3]);
        }
    }
}

// ---------------------------------------------------------------------------
// Transpose G[b*1024+t][j] -> Gt[t][j][b], adding bias per j.
// ---------------------------------------------------------------------------
__global__ void __launch_bounds__(256) transp(
    const float* __restrict__ bif, const float* __restrict__ bhf,
    const float* __restrict__ bib, const float* __restrict__ bhb) {
    __shared__ float tile[64][65];
    const int t  = blockIdx.y;
    const int j0 = blockIdx.x * 64;
    const int tid = threadIdx.x;

    const int jq = (tid & 15) * 4;
    const int bb = tid >> 4;
#pragma unroll
    for (int p = 0; p < 4; p++) {
        int bi = bb + p * 16;
        float4 v = *(const float4*)(G_buf + ((size_t)(bi * 1024 + t)) * 2048 + j0 + jq);
        tile[bi][jq + 0] = v.x; tile[bi][jq + 1] = v.y;
        tile[bi][jq + 2] = v.z; tile[bi][jq + 3] = v.w;
    }
    __syncthreads();

    const int bq = (tid & 15) * 4;
    const int jj = tid >> 4;
#pragma unroll
    for (int p = 0; p < 4; p++) {
        int j = jj + p * 16;
        int jg = j0 + j;
        float bias = (jg < 1024) ? (bif[jg] + bhf[jg])
                                 : (bib[jg - 1024] + bhb[jg - 1024]);
        float4 v = make_float4(tile[bq + 0][j] + bias, tile[bq + 1][j] + bias,
                               tile[bq + 2][j] + bias, tile[bq + 3][j] + bias);
        *(float4*)(Gt_buf + ((size_t)t * 2048 + j0 + j) * 64 + bq) = v;
    }
}

// ---------------------------------------------------------------------------
// Phase 2: persistent recurrence — exact R9 (proven 5.5us/step).
// ---------------------------------------------------------------------------
__global__ void __launch_bounds__(256, 1) recur(
    const float* __restrict__ Whf, const float* __restrict__ Whb)
{
    extern __shared__ float sm[];
    float* h_s = sm;                                     // [256 k][16 b] 16KB
    ulonglong2* w_s = (ulonglong2*)(sm + 4096);          // [16 q][256 k] 64KB
    unsigned long long* red = (unsigned long long*)(sm + 4096 + 16384); // 12KB

    const int cta = blockIdx.x;
    const int dir = cta >> 6;
    const int grp = cta & 63;
    const int bg  = grp >> 4;
    const int qs  = grp & 15;
    const int b0  = bg * 16;
    const int qb  = qs * 16;
    const int tid = threadIdx.x;
    const int b   = tid & 15;
    const int qq  = (tid >> 4) & 3;
    const int kh  = tid >> 6;
    const bool lo = (kh == 0);
    const int bglob = b0 + b;

    const float* W = dir ? Whb : Whf;
    for (int idx = tid; idx < 4096; idx += 256) {
        int q_loc = idx >> 8;
        int k     = idx & 255;
        int qg    = qb + q_loc;
        ulonglong2 v;
        v.x = pk2(W[(size_t)(      qg) * 256 + k], W[(size_t)(256 + qg) * 256 + k]);
        v.y = pk2(W[(size_t)(512 + qg) * 256 + k], W[(size_t)(768 + qg) * 256 + k]);
        w_s[idx] = v;
    }

    float cs[4] = {0.f, 0.f, 0.f, 0.f};

    int t = dir ? 1023 : 0;
    float pi[4], pf[4], pg[4], po[4];
    if (lo) {
        const float* gp = Gt_buf + ((size_t)t * 2048 + (size_t)dir * 1024) * 64 + bglob;
#pragma unroll
        for (int j = 0; j < 4; j++) {
            int qg = qb + qq * 4 + j;
            pi[j] = __ldg(gp + (size_t)(      qg) * 64);
            pf[j] = __ldg(gp + (size_t)(256 + qg) * 64);
            pg[j] = __ldg(gp + (size_t)(512 + qg) * 64);
            po[j] = __ldg(gp + (size_t)(768 + qg) * 64);
        }
    }
    __syncthreads();

    float* Hd = Hhist + (size_t)dir * 1024 * 16384;
    const int bar_id = kh + 1;
    const int lcl = tid & 63;

    for (int step = 0; step < 1024; ++step) {
        float4* dstq = (float4*)h_s + kh * 256;
        if (step == 0) {
            float4 z = make_float4(0.f, 0.f, 0.f, 0.f);
#pragma unroll
            for (int i = 0; i < 4; i++) dstq[lcl + i * 64] = z;
        } else {
            const int tp = dir ? (t + 1) : (t - 1);
            const float4* srcb = (const float4*)(Hd + (size_t)tp * 16384);
#pragma unroll
            for (int i = 0; i < 4; i++) {
                int idx = lcl + i * 64;
                int kl  = idx >> 2;
                int c   = idx & 3;
                cp16(dstq + idx, srcb + (size_t)(kh * 64 + kl) * 16 + (b0 >> 2) + c);
            }
            asm volatile("cp.async.commit_group;");
            asm volatile("cp.async.wait_group 0;" ::: "memory");
        }
        asm volatile("bar.sync %0, 64;" :: "r"(bar_id) : "memory");

        unsigned long long aif[4], ago[4];
        if (lo) {
#pragma unroll
            for (int j = 0; j < 4; j++) {
                aif[j] = pk2(pi[j], pf[j]);
                ago[j] = pk2(pg[j], po[j]);
            }
        } else {
#pragma unroll
            for (int j = 0; j < 4; j++) { aif[j] = 0ull; ago[j] = 0ull; }
        }

        const float* hq = h_s + kh * 64 * 16 + b;
        const ulonglong2* wq = w_s + (qq * 4) * 256 + kh * 64;
#pragma unroll 8
        for (int kk = 0; kk < 64; ++kk) {
            float hv = hq[kk * 16];
            unsigned long long hh = pk2(hv, hv);
#pragma unroll
            for (int j = 0; j < 4; j++) {
                ulonglong2 wv = wq[j * 256 + kk];
                aif[j] = fma2(hh, wv.x, aif[j]);
                ago[j] = fma2(hh, wv.y, ago[j]);
            }
        }

        if (!lo) {
            int base = (kh - 1) * 64 + lcl;
#pragma unroll
            for (int j = 0; j < 4; j++) {
                red[(2 * j    ) * 192 + base] = aif[j];
                red[(2 * j + 1) * 192 + base] = ago[j];
            }
        }
        __syncthreads();

        if (lo) {
#pragma unroll
            for (int j = 0; j < 4; j++) {
#pragma unroll
                for (int g = 0; g < 3; g++) {
                    aif[j] = add2(aif[j], red[(2 * j    ) * 192 + g * 64 + tid]);
                    ago[j] = add2(ago[j], red[(2 * j + 1) * 192 + g * 64 + tid]);
                }
            }
            float* hd = Hd + (size_t)t * 16384;
#pragma unroll
            for (int j = 0; j < 4; j++) {
                float2 vif = upk(aif[j]), vgo = upk(ago[j]);
                float ig = sigm_f(vif.x), fg = sigm_f(vif.y);
                float gg = tanh_f(vgo.x), og = sigm_f(vgo.y);
                cs[j] = fg * cs[j] + ig * gg;
                float hn = og * tanh_f(cs[j]);
                __stcg(hd + (qb + qq * 4 + j) * 64 + bglob, hn);
            }
        }

        if (step == 1023) break;

        __threadfence();
        __syncthreads();
        if (tid == 0) st_rel(&g_arrive[dir][bg][qs][0], (unsigned)(step + 1));

        t = dir ? (1022 - step) : (step + 1);
        if (lo) {
            const float* gp = Gt_buf + ((size_t)t * 2048 + (size_t)dir * 1024) * 64 + bglob;
#pragma unroll
            for (int j = 0; j < 4; j++) {
                int qg = qb + qq * 4 + j;
                pi[j] = __ldg(gp + (size_t)(      qg) * 64);
                pf[j] = __ldg(gp + (size_t)(256 + qg) * 64);
                pg[j] = __ldg(gp + (size_t)(512 + qg) * 64);
                po[j] = __ldg(gp + (size_t)(768 + qg) * 64);
            }
        }

        if (kh == 1 && lcl < 16) {
            while (ld_acq(&g_arrive[dir][bg][lcl][0]) <= (unsigned)step) {}
        }
        __syncthreads();
    }
}

// ---------------------------------------------------------------------------
// Final: out[b][t][dir*256+q] = Hhist[dir][t][q*64+b]
// ---------------------------------------------------------------------------
__global__ void __launch_bounds__(256) out_tr(float* __restrict__ out) {
    __shared__ float tile[64][65];
    const int q0  = blockIdx.x * 64;
    const int t   = blockIdx.y;
    const int dir = blockIdx.z;
    const int tid = threadIdx.x;

    const float* src = Hhist + ((size_t)dir * 1024 + t) * 16384;
    const int b  = tid & 63;
    const int q4 = (tid >> 6) * 16;
#pragma unroll
    for (int i = 0; i < 16; i++) {
        int qq = q4 + i;
        tile[b][qq] = src[(q0 + qq) * 64 + b];
    }
    __syncthreads();

    const int qs = (tid & 15) * 4;
    const int br = tid >> 4;
#pragma unroll
    for (int p = 0; p < 4; p++) {
        int bb = br + p * 16;
        float4 v = make_float4(tile[bb][qs + 0], tile[bb][qs + 1],
                               tile[bb][qs + 2], tile[bb][qs + 3]);
        *(float4*)(out + ((size_t)bb * 1024 + t) * 512 + dir * 256 + q0 + qs) = v;
    }
}

// ---------------------------------------------------------------------------
extern "C" void kernel_launch(void* const* d_in, const int* in_sizes, int n_in,
                              void* d_out, int out_size) {
    const float* x   = (const float*)d_in[0];
    const float* Wif = (const float*)d_in[1];
    const float* Whf = (const float*)d_in[2];
    const float* bif = (const float*)d_in[3];
    const float* bhf = (const float*)d_in[4];
    const float* Wib = (const float*)d_in[5];
    const float* Whb = (const float*)d_in[6];
    const float* bib = (const float*)d_in[7];
    const float* bhb = (const float*)d_in[8];
    float* out = (float*)d_out;

    cudaFuncSetAttribute(recur,    cudaFuncAttributeMaxDynamicSharedMemorySize, 94208);
    cudaFuncSetAttribute(gemm_mma, cudaFuncAttributeMaxDynamicSharedMemorySize, 73728);

    reset_k<<<16, 256>>>();
    convA<<<65536, 256>>>(x);
    convW<<<2048, 256>>>(Wif, Wib);
    gemm_mma<<<dim3(16, 512), 256, 73728>>>();
    transp<<<dim3(32, 1024), 256>>>(bif, bhf, bib, bhb);
    recur<<<128, 256, 94208>>>(Whf, Whb);
    out_tr<<<dim3(4, 1024, 2), 256>>>(out);
}

// round 15
// speedup vs baseline: 1.6745x; 1.0002x over previous
#include <cuda_runtime.h>
#include <cuda_bf16.h>
#include <cstdint>

// Sizes (fixed): B=64, T=1024, D=512, H=256, 4H=1024, two directions.

__device__ float G_buf [(size_t)65536 * 2048];        // [m = b*1024 + t][j]
__device__ float Gt_buf[(size_t)1024 * 2048 * 64];    // [t][j][b]
__device__ float Hhist [(size_t)2 * 1024 * 16384];    // [dir][t][q*64 + b]
__device__ unsigned g_arrive[2][4][16][32];           // [dir][bgroup][qslice][pad]
__device__ __align__(16) __nv_bfloat16 Abuf[(size_t)65536 * 1536]; // [m][hi|hi|lo]
__device__ __align__(16) __nv_bfloat16 Wbuf[(size_t)2048 * 1536];  // [j][Whi|Wlo|Whi]

// ---------------------------------------------------------------------------
static __device__ __forceinline__ unsigned long long pk2(float x, float y) {
    unsigned long long r;
    asm("mov.b64 %0, {%1, %2};" : "=l"(r) : "f"(x), "f"(y));
    return r;
}
static __device__ __forceinline__ unsigned long long fma2(
    unsigned long long a, unsigned long long b, unsigned long long c) {
    unsigned long long d;
    asm("fma.rn.f32x2 %0, %1, %2, %3;" : "=l"(d) : "l"(a), "l"(b), "l"(c));
    return d;
}
static __device__ __forceinline__ unsigned long long add2(
    unsigned long long a, unsigned long long b) {
    unsigned long long d;
    asm("add.rn.f32x2 %0, %1, %2;" : "=l"(d) : "l"(a), "l"(b));
    return d;
}
static __device__ __forceinline__ float2 upk(unsigned long long v) {
    float2 r;
    asm("mov.b64 {%0, %1}, %2;" : "=f"(r.x), "=f"(r.y) : "l"(v));
    return r;
}
static __device__ __forceinline__ float sigm_f(float x) {
    return __frcp_rn(1.f + __expf(-x));
}
static __device__ __forceinline__ float tanh_f(float x) {
    x = fminf(fmaxf(x, -15.f), 15.f);
    float e = __expf(2.f * x);
    return (e - 1.f) / (e + 1.f);
}
static __device__ __forceinline__ void st_rel(unsigned* p, unsigned v) {
    asm volatile("st.release.gpu.u32 [%0], %1;" :: "l"(p), "r"(v) : "memory");
}
static __device__ __forceinline__ unsigned ld_acq(const unsigned* p) {
    unsigned v;
    asm volatile("ld.acquire.gpu.u32 %0, [%1];" : "=r"(v) : "l"(p) : "memory");
    return v;
}
static __device__ __forceinline__ void cp16(void* smem_dst, const void* gsrc) {
    unsigned s = (unsigned)__cvta_generic_to_shared(smem_dst);
    asm volatile("cp.async.cg.shared.global [%0], [%1], 16;" :: "r"(s), "l"(gsrc));
}

// mma.sync m16n8k16 bf16 (baseline tensor ISA; compiles for compute_103)
static __device__ __forceinline__ void mma_bf16(
    float& c0, float& c1, float& c2, float& c3,
    uint32_t a0, uint32_t a1, uint32_t a2, uint32_t a3,
    uint32_t b0, uint32_t b1) {
    asm volatile(
        "mma.sync.aligned.m16n8k16.row.col.f32.bf16.bf16.f32 "
        "{%0,%1,%2,%3}, {%4,%5,%6,%7}, {%8,%9}, {%0,%1,%2,%3};"
        : "+f"(c0), "+f"(c1), "+f"(c2), "+f"(c3)
        : "r"(a0), "r"(a1), "r"(a2), "r"(a3), "r"(b0), "r"(b1));
}

// ---------------------------------------------------------------------------
__global__ void reset_k() {
    unsigned i = blockIdx.x * 256u + threadIdx.x;
    if (i < 4096u) (&g_arrive[0][0][0][0])[i] = 0u;
}

// ---------------------------------------------------------------------------
// bf16 split conversions: x -> Abuf = [hi|hi|lo], W -> Wbuf = [Whi|Wlo|Whi]
// ---------------------------------------------------------------------------
__global__ void __launch_bounds__(256) convA(const float* __restrict__ x) {
    const int row = blockIdx.x;
    const int t   = threadIdx.x;
    float2 v = *(const float2*)(x + (size_t)row * 512 + t * 2);
    __nv_bfloat16 h0 = __float2bfloat16(v.x);
    __nv_bfloat16 h1 = __float2bfloat16(v.y);
    __nv_bfloat16 l0 = __float2bfloat16(v.x - __bfloat162float(h0));
    __nv_bfloat16 l1 = __float2bfloat16(v.y - __bfloat162float(h1));
    __nv_bfloat162 hh; hh.x = h0; hh.y = h1;
    __nv_bfloat162 ll; ll.x = l0; ll.y = l1;
    __nv_bfloat162* dst = (__nv_bfloat162*)(Abuf + (size_t)row * 1536);
    dst[t] = hh; dst[256 + t] = hh; dst[512 + t] = ll;
}
__global__ void __launch_bounds__(256) convW(
    const float* __restrict__ Wf, const float* __restrict__ Wb) {
    const int j = blockIdx.x;
    const int t = threadIdx.x;
    const float* src = (j < 1024) ? (Wf + (size_t)j * 512)
                                  : (Wb + (size_t)(j - 1024) * 512);
    float2 v = *(const float2*)(src + t * 2);
    __nv_bfloat16 h0 = __float2bfloat16(v.x);
    __nv_bfloat16 h1 = __float2bfloat16(v.y);
    __nv_bfloat16 l0 = __float2bfloat16(v.x - __bfloat162float(h0));
    __nv_bfloat16 l1 = __float2bfloat16(v.y - __bfloat162float(h1));
    __nv_bfloat162 hh; hh.x = h0; hh.y = h1;
    __nv_bfloat162 ll; ll.x = l0; ll.y = l1;
    __nv_bfloat162* dst = (__nv_bfloat162*)(Wbuf + (size_t)j * 1536);
    dst[t] = hh; dst[256 + t] = ll; dst[512 + t] = hh;
}

// ---------------------------------------------------------------------------
// Tensor-core GEMM: G[m][j] = A'[m,:] . W'[j,:], K'=1536, fp32 accum.
// CTA tile 128x128, 8 warps (2m x 4n), warp tile 64x32. (R14, proven)
// ---------------------------------------------------------------------------
static constexpr int KS = 72;   // smem k-stride (bf16 units)

__global__ void __launch_bounds__(256, 1) gemm_mma() {
    extern __shared__ __align__(16) __nv_bfloat16 smb[];
    __nv_bfloat16* As[2] = { smb,          smb + 9216  };
    __nv_bfloat16* Ws[2] = { smb + 18432,  smb + 27648 };

    const int tid = threadIdx.x;
    const int wid = tid >> 5;
    const int lane = tid & 31;
    const int gid = lane >> 2;
    const int tig = lane & 3;
    const int wm = wid >> 2;
    const int wn = wid & 3;
    const int n0 = blockIdx.x * 128;
    const int m0 = blockIdx.y * 128;

    float acc[4][4][4];
#pragma unroll
    for (int i = 0; i < 4; i++)
#pragma unroll
        for (int j = 0; j < 4; j++)
#pragma unroll
            for (int k = 0; k < 4; k++) acc[i][j][k] = 0.f;

    auto load_stage = [&](int s, int kc) {
        const __nv_bfloat16* Ag = Abuf + (size_t)m0 * 1536 + kc * 64;
        const __nv_bfloat16* Wg = Wbuf + (size_t)n0 * 1536 + kc * 64;
#pragma unroll
        for (int i = 0; i < 4; i++) {
            int idx = tid + i * 256;
            int row = idx >> 3, seg = idx & 7;
            cp16(As[s] + row * KS + seg * 8, Ag + (size_t)row * 1536 + seg * 8);
            cp16(Ws[s] + row * KS + seg * 8, Wg + (size_t)row * 1536 + seg * 8);
        }
        asm volatile("cp.async.commit_group;");
    };

    load_stage(0, 0);

    for (int kc = 0; kc < 24; ++kc) {
        const int s = kc & 1;
        if (kc + 1 < 24) load_stage(s ^ 1, kc + 1);
        if (kc + 1 < 24) asm volatile("cp.async.wait_group 1;" ::: "memory");
        else             asm volatile("cp.async.wait_group 0;" ::: "memory");
        __syncthreads();

        const __nv_bfloat16* Ab = As[s] + (wm * 64 + gid) * KS + tig * 2;
        const __nv_bfloat16* Wb2 = Ws[s] + (wn * 32 + gid) * KS + tig * 2;

#pragma unroll
        for (int kk = 0; kk < 4; ++kk) {
            const int k0 = kk * 16;
            uint32_t a[4][4];
#pragma unroll
            for (int mt = 0; mt < 4; mt++) {
                const __nv_bfloat16* p = Ab + mt * 16 * KS + k0;
                a[mt][0] = *(const uint32_t*)(p);
                a[mt][1] = *(const uint32_t*)(p + 8 * KS);
                a[mt][2] = *(const uint32_t*)(p + 8);
                a[mt][3] = *(const uint32_t*)(p + 8 * KS + 8);
            }
            uint32_t bf[4][2];
#pragma unroll
            for (int nt = 0; nt < 4; nt++) {
                const __nv_bfloat16* p = Wb2 + nt * 8 * KS + k0;
                bf[nt][0] = *(const uint32_t*)(p);
                bf[nt][1] = *(const uint32_t*)(p + 8);
            }
#pragma unroll
            for (int mt = 0; mt < 4; mt++)
#pragma unroll
                for (int nt = 0; nt < 4; nt++)
                    mma_bf16(acc[mt][nt][0], acc[mt][nt][1],
                             acc[mt][nt][2], acc[mt][nt][3],
                             a[mt][0], a[mt][1], a[mt][2], a[mt][3],
                             bf[nt][0], bf[nt][1]);
        }
        __syncthreads();
    }

#pragma unroll
    for (int mt = 0; mt < 4; mt++) {
        int mrow = m0 + wm * 64 + mt * 16 + gid;
#pragma unroll
        for (int nt = 0; nt < 4; nt++) {
            int ncol = n0 + wn * 32 + nt * 8 + tig * 2;
            float* d0 = G_buf + (size_t)mrow * 2048 + ncol;
            float* d1 = G_buf + (size_t)(mrow + 8) * 2048 + ncol;
            *(float2*)d0 = make_float2(acc[mt][nt][0], acc[mt][nt][1]);
            *(float2*)d1 = make_float2(acc[mt][nt][2], acc[mt][nt][3]);
        }
    }
}

// ---------------------------------------------------------------------------
// Transpose G[b*1024+t][j] -> Gt[t][j][b], adding bias per j.
// ---------------------------------------------------------------------------
__global__ void __launch_bounds__(256) transp(
    const float* __restrict__ bif, const float* __restrict__ bhf,
    const float* __restrict__ bib, const float* __restrict__ bhb) {
    __shared__ float tile[64][65];
    const int t  = blockIdx.y;
    const int j0 = blockIdx.x * 64;
    const int tid = threadIdx.x;

    const int jq = (tid & 15) * 4;
    const int bb = tid >> 4;
#pragma unroll
    for (int p = 0; p < 4; p++) {
        int bi = bb + p * 16;
        float4 v = *(const float4*)(G_buf + ((size_t)(bi * 1024 + t)) * 2048 + j0 + jq);
        tile[bi][jq + 0] = v.x; tile[bi][jq + 1] = v.y;
        tile[bi][jq + 2] = v.z; tile[bi][jq + 3] = v.w;
    }
    __syncthreads();

    const int bq = (tid & 15) * 4;
    const int jj = tid >> 4;
#pragma unroll
    for (int p = 0; p < 4; p++) {
        int j = jj + p * 16;
        int jg = j0 + j;
        float bias = (jg < 1024) ? (bif[jg] + bhf[jg])
                                 : (bib[jg - 1024] + bhb[jg - 1024]);
        float4 v = make_float4(tile[bq + 0][j] + bias, tile[bq + 1][j] + bias,
                               tile[bq + 2][j] + bias, tile[bq + 3][j] + bias);
        *(float4*)(Gt_buf + ((size_t)t * 2048 + j0 + j) * 64 + bq) = v;
    }
}

// ---------------------------------------------------------------------------
// Phase 2: persistent recurrence (R9 skeleton). ONE change vs R14:
// w_s qq-block stride padded 1024 -> 1025 entries (16400B, mod 128 = 16) so
// the two qq groups inside a warp hit disjoint bank quads -> w-broadcast LDS
// goes from 2 wavefronts to 1 (w LDS dominate the k-loop).
// ---------------------------------------------------------------------------
__global__ void __launch_bounds__(256, 1) recur(
    const float* __restrict__ Whf, const float* __restrict__ Whb)
{
    extern __shared__ float sm[];
    float* h_s = sm;                                     // [256 k][16 b] 16KB
    ulonglong2* w_s = (ulonglong2*)(sm + 4096);          // 4*1025+... = 4100 ent, 65600B
    unsigned long long* red = (unsigned long long*)((char*)sm + 16384 + 65600); // 12KB

    const int cta = blockIdx.x;
    const int dir = cta >> 6;
    const int grp = cta & 63;
    const int bg  = grp >> 4;
    const int qs  = grp & 15;
    const int b0  = bg * 16;
    const int qb  = qs * 16;
    const int tid = threadIdx.x;
    const int b   = tid & 15;
    const int qq  = (tid >> 4) & 3;
    const int kh  = tid >> 6;
    const bool lo = (kh == 0);
    const int bglob = b0 + b;

    // Fill w_s: entry = qq*1025 + j*256 + k for q = qb + qq*4 + j
    const float* W = dir ? Whb : Whf;
    for (int idx = tid; idx < 4096; idx += 256) {
        int q_loc = idx >> 8;           // 0..15
        int k     = idx & 255;
        int eqq   = q_loc >> 2;
        int ej    = q_loc & 3;
        int qg    = qb + q_loc;
        ulonglong2 v;
        v.x = pk2(W[(size_t)(      qg) * 256 + k], W[(size_t)(256 + qg) * 256 + k]);
        v.y = pk2(W[(size_t)(512 + qg) * 256 + k], W[(size_t)(768 + qg) * 256 + k]);
        w_s[eqq * 1025 + ej * 256 + k] = v;
    }

    float cs[4] = {0.f, 0.f, 0.f, 0.f};

    int t = dir ? 1023 : 0;
    float pi[4], pf[4], pg[4], po[4];
    if (lo) {
        const float* gp = Gt_buf + ((size_t)t * 2048 + (size_t)dir * 1024) * 64 + bglob;
#pragma unroll
        for (int j = 0; j < 4; j++) {
            int qg = qb + qq * 4 + j;
            pi[j] = __ldg(gp + (size_t)(      qg) * 64);
            pf[j] = __ldg(gp + (size_t)(256 + qg) * 64);
            pg[j] = __ldg(gp + (size_t)(512 + qg) * 64);
            po[j] = __ldg(gp + (size_t)(768 + qg) * 64);
        }
    }
    __syncthreads();

    float* Hd = Hhist + (size_t)dir * 1024 * 16384;
    const int bar_id = kh + 1;
    const int lcl = tid & 63;

    for (int step = 0; step < 1024; ++step) {
        float4* dstq = (float4*)h_s + kh * 256;
        if (step == 0) {
            float4 z = make_float4(0.f, 0.f, 0.f, 0.f);
#pragma unroll
            for (int i = 0; i < 4; i++) dstq[lcl + i * 64] = z;
        } else {
            const int tp = dir ? (t + 1) : (t - 1);
            const float4* srcb = (const float4*)(Hd + (size_t)tp * 16384);
#pragma unroll
            for (int i = 0; i < 4; i++) {
                int idx = lcl + i * 64;
                int kl  = idx >> 2;
                int c   = idx & 3;
                cp16(dstq + idx, srcb + (size_t)(kh * 64 + kl) * 16 + (b0 >> 2) + c);
            }
            asm volatile("cp.async.commit_group;");
            asm volatile("cp.async.wait_group 0;" ::: "memory");
        }
        asm volatile("bar.sync %0, 64;" :: "r"(bar_id) : "memory");

        unsigned long long aif[4], ago[4];
        if (lo) {
#pragma unroll
            for (int j = 0; j < 4; j++) {
                aif[j] = pk2(pi[j], pf[j]);
                ago[j] = pk2(pg[j], po[j]);
            }
        } else {
#pragma unroll
            for (int j = 0; j < 4; j++) { aif[j] = 0ull; ago[j] = 0ull; }
        }

        const float* hq = h_s + kh * 64 * 16 + b;
        const ulonglong2* wq = w_s + qq * 1025 + kh * 64;
#pragma unroll 8
        for (int kk = 0; kk < 64; ++kk) {
            float hv = hq[kk * 16];
            unsigned long long hh = pk2(hv, hv);
#pragma unroll
            for (int j = 0; j < 4; j++) {
                ulonglong2 wv = wq[j * 256 + kk];
                aif[j] = fma2(hh, wv.x, aif[j]);
                ago[j] = fma2(hh, wv.y, ago[j]);
            }
        }

        if (!lo) {
            int base = (kh - 1) * 64 + lcl;
#pragma unroll
            for (int j = 0; j < 4; j++) {
                red[(2 * j    ) * 192 + base] = aif[j];
                red[(2 * j + 1) * 192 + base] = ago[j];
            }
        }
        __syncthreads();

        if (lo) {
#pragma unroll
            for (int j = 0; j < 4; j++) {
#pragma unroll
                for (int g = 0; g < 3; g++) {
                    aif[j] = add2(aif[j], red[(2 * j    ) * 192 + g * 64 + tid]);
                    ago[j] = add2(ago[j], red[(2 * j + 1) * 192 + g * 64 + tid]);
                }
            }
            float* hd = Hd + (size_t)t * 16384;
#pragma unroll
            for (int j = 0; j < 4; j++) {
                float2 vif = upk(aif[j]), vgo = upk(ago[j]);
                float ig = sigm_f(vif.x), fg = sigm_f(vif.y);
                float gg = tanh_f(vgo.x), og = sigm_f(vgo.y);
                cs[j] = fg * cs[j] + ig * gg;
                float hn = og * tanh_f(cs[j]);
                __stcg(hd + (qb + qq * 4 + j) * 64 + bglob, hn);
            }
        }

        if (step == 1023) break;

        __threadfence();
        __syncthreads();
        if (tid == 0) st_rel(&g_arrive[dir][bg][qs][0], (unsigned)(step + 1));

        t = dir ? (1022 - step) : (step + 1);
        if (lo) {
            const float* gp = Gt_buf + ((size_t)t * 2048 + (size_t)dir * 1024) * 64 + bglob;
#pragma unroll
            for (int j = 0; j < 4; j++) {
                int qg = qb + qq * 4 + j;
                pi[j] = __ldg(gp + (size_t)(      qg) * 64);
                pf[j] = __ldg(gp + (size_t)(256 + qg) * 64);
                pg[j] = __ldg(gp + (size_t)(512 + qg) * 64);
                po[j] = __ldg(gp + (size_t)(768 + qg) * 64);
            }
        }

        if (kh == 1 && lcl < 16) {
            while (ld_acq(&g_arrive[dir][bg][lcl][0]) <= (unsigned)step) {}
        }
        __syncthreads();
    }
}

// ---------------------------------------------------------------------------
// Final: out[b][t][dir*256+q] = Hhist[dir][t][q*64+b]
// ---------------------------------------------------------------------------
__global__ void __launch_bounds__(256) out_tr(float* __restrict__ out) {
    __shared__ float tile[64][65];
    const int q0  = blockIdx.x * 64;
    const int t   = blockIdx.y;
    const int dir = blockIdx.z;
    const int tid = threadIdx.x;

    const float* src = Hhist + ((size_t)dir * 1024 + t) * 16384;
    const int b  = tid & 63;
    const int q4 = (tid >> 6) * 16;
#pragma unroll
    for (int i = 0; i < 16; i++) {
        int qq = q4 + i;
        tile[b][qq] = src[(q0 + qq) * 64 + b];
    }
    __syncthreads();

    const int qs = (tid & 15) * 4;
    const int br = tid >> 4;
#pragma unroll
    for (int p = 0; p < 4; p++) {
        int bb = br + p * 16;
        float4 v = make_float4(tile[bb][qs + 0], tile[bb][qs + 1],
                               tile[bb][qs + 2], tile[bb][qs + 3]);
        *(float4*)(out + ((size_t)bb * 1024 + t) * 512 + dir * 256 + q0 + qs) = v;
    }
}

// ---------------------------------------------------------------------------
extern "C" void kernel_launch(void* const* d_in, const int* in_sizes, int n_in,
                              void* d_out, int out_size) {
    const float* x   = (const float*)d_in[0];
    const float* Wif = (const float*)d_in[1];
    const float* Whf = (const float*)d_in[2];
    const float* bif = (const float*)d_in[3];
    const float* bhf = (const float*)d_in[4];
    const float* Wib = (const float*)d_in[5];
    const float* Whb = (const float*)d_in[6];
    const float* bib = (const float*)d_in[7];
    const float* bhb = (const float*)d_in[8];
    float* out = (float*)d_out;

    // recur smem: 16384 (h) + 65600 (w padded) + 12288 (red) = 94272
    cudaFuncSetAttribute(recur,    cudaFuncAttributeMaxDynamicSharedMemorySize, 94272);
    cudaFuncSetAttribute(gemm_mma, cudaFuncAttributeMaxDynamicSharedMemorySize, 73728);

    reset_k<<<16, 256>>>();
    convA<<<65536, 256>>>(x);
    convW<<<2048, 256>>>(Wif, Wib);
    gemm_mma<<<dim3(16, 512), 256, 73728>>>();
    transp<<<dim3(32, 1024), 256>>>(bif, bhf, bib, bhb);
    recur<<<128, 256, 94272>>>(Whf, Whb);
    out_tr<<<dim3(4, 1024, 2), 256>>>(out);
}

// round 16
// speedup vs baseline: 2.0341x; 1.2148x over previous
#include <cuda_runtime.h>
#include <cuda_bf16.h>
#include <cstdint>

// Sizes (fixed): B=64, T=1024, D=512, H=256, 4H=1024, two directions.

__device__ float G_buf [(size_t)65536 * 2048];        // [m = b*1024 + t][j]
__device__ float Gt_buf[(size_t)1024 * 2048 * 64];    // [t][j][b]
__device__ float Hhist [(size_t)2 * 1024 * 16384];    // [dir][t][q*64 + b]
__device__ unsigned g_arrive[2][4][16][32];           // [dir][bgroup][qslice][pad]
__device__ __align__(16) __nv_bfloat16 Abuf[(size_t)65536 * 1536]; // [m][hi|hi|lo]
__device__ __align__(16) __nv_bfloat16 Wbuf[(size_t)2048 * 1536];  // [j][Whi|Wlo|Whi]

// ---------------------------------------------------------------------------
static __device__ __forceinline__ float sigm_f(float x) {
    return __frcp_rn(1.f + __expf(-x));
}
static __device__ __forceinline__ float tanh_f(float x) {
    x = fminf(fmaxf(x, -15.f), 15.f);
    float e = __expf(2.f * x);
    return (e - 1.f) / (e + 1.f);
}
static __device__ __forceinline__ void st_rel(unsigned* p, unsigned v) {
    asm volatile("st.release.gpu.u32 [%0], %1;" :: "l"(p), "r"(v) : "memory");
}
static __device__ __forceinline__ unsigned ld_acq(const unsigned* p) {
    unsigned v;
    asm volatile("ld.acquire.gpu.u32 %0, [%1];" : "=r"(v) : "l"(p) : "memory");
    return v;
}
static __device__ __forceinline__ void cp16(void* smem_dst, const void* gsrc) {
    unsigned s = (unsigned)__cvta_generic_to_shared(smem_dst);
    asm volatile("cp.async.cg.shared.global [%0], [%1], 16;" :: "r"(s), "l"(gsrc));
}
static __device__ __forceinline__ uint32_t pkbf(__nv_bfloat16 a, __nv_bfloat16 b) {
    __nv_bfloat162 t; t.x = a; t.y = b;
    return *(uint32_t*)&t;
}

// mma.sync m16n8k16 bf16 (baseline tensor ISA; compiles for compute_103)
static __device__ __forceinline__ void mma_bf16(
    float& c0, float& c1, float& c2, float& c3,
    uint32_t a0, uint32_t a1, uint32_t a2, uint32_t a3,
    uint32_t b0, uint32_t b1) {
    asm volatile(
        "mma.sync.aligned.m16n8k16.row.col.f32.bf16.bf16.f32 "
        "{%0,%1,%2,%3}, {%4,%5,%6,%7}, {%8,%9}, {%0,%1,%2,%3};"
        : "+f"(c0), "+f"(c1), "+f"(c2), "+f"(c3)
        : "r"(a0), "r"(a1), "r"(a2), "r"(a3), "r"(b0), "r"(b1));
}

// ---------------------------------------------------------------------------
__global__ void reset_k() {
    unsigned i = blockIdx.x * 256u + threadIdx.x;
    if (i < 4096u) (&g_arrive[0][0][0][0])[i] = 0u;
}

// ---------------------------------------------------------------------------
// bf16 split conversions: x -> Abuf = [hi|hi|lo], W -> Wbuf = [Whi|Wlo|Whi]
// ---------------------------------------------------------------------------
__global__ void __launch_bounds__(256) convA(const float* __restrict__ x) {
    const int row = blockIdx.x;
    const int t   = threadIdx.x;
    float2 v = *(const float2*)(x + (size_t)row * 512 + t * 2);
    __nv_bfloat16 h0 = __float2bfloat16(v.x);
    __nv_bfloat16 h1 = __float2bfloat16(v.y);
    __nv_bfloat16 l0 = __float2bfloat16(v.x - __bfloat162float(h0));
    __nv_bfloat16 l1 = __float2bfloat16(v.y - __bfloat162float(h1));
    __nv_bfloat162 hh; hh.x = h0; hh.y = h1;
    __nv_bfloat162 ll; ll.x = l0; ll.y = l1;
    __nv_bfloat162* dst = (__nv_bfloat162*)(Abuf + (size_t)row * 1536);
    dst[t] = hh; dst[256 + t] = hh; dst[512 + t] = ll;
}
__global__ void __launch_bounds__(256) convW(
    const float* __restrict__ Wf, const float* __restrict__ Wb) {
    const int j = blockIdx.x;
    const int t = threadIdx.x;
    const float* src = (j < 1024) ? (Wf + (size_t)j * 512)
                                  : (Wb + (size_t)(j - 1024) * 512);
    float2 v = *(const float2*)(src + t * 2);
    __nv_bfloat16 h0 = __float2bfloat16(v.x);
    __nv_bfloat16 h1 = __float2bfloat16(v.y);
    __nv_bfloat16 l0 = __float2bfloat16(v.x - __bfloat162float(h0));
    __nv_bfloat16 l1 = __float2bfloat16(v.y - __bfloat162float(h1));
    __nv_bfloat162 hh; hh.x = h0; hh.y = h1;
    __nv_bfloat162 ll; ll.x = l0; ll.y = l1;
    __nv_bfloat162* dst = (__nv_bfloat162*)(Wbuf + (size_t)j * 1536);
    dst[t] = hh; dst[256 + t] = ll; dst[512 + t] = hh;
}

// ---------------------------------------------------------------------------
// Tensor-core GEMM: G[m][j] = A'[m,:] . W'[j,:], K'=1536 (R14, proven)
// ---------------------------------------------------------------------------
static constexpr int KS = 72;

__global__ void __launch_bounds__(256, 1) gemm_mma() {
    extern __shared__ __align__(16) __nv_bfloat16 smb[];
    __nv_bfloat16* As[2] = { smb,          smb + 9216  };
    __nv_bfloat16* Ws[2] = { smb + 18432,  smb + 27648 };

    const int tid = threadIdx.x;
    const int wid = tid >> 5;
    const int lane = tid & 31;
    const int gid = lane >> 2;
    const int tig = lane & 3;
    const int wm = wid >> 2;
    const int wn = wid & 3;
    const int n0 = blockIdx.x * 128;
    const int m0 = blockIdx.y * 128;

    float acc[4][4][4];
#pragma unroll
    for (int i = 0; i < 4; i++)
#pragma unroll
        for (int j = 0; j < 4; j++)
#pragma unroll
            for (int k = 0; k < 4; k++) acc[i][j][k] = 0.f;

    auto load_stage = [&](int s, int kc) {
        const __nv_bfloat16* Ag = Abuf + (size_t)m0 * 1536 + kc * 64;
        const __nv_bfloat16* Wg = Wbuf + (size_t)n0 * 1536 + kc * 64;
#pragma unroll
        for (int i = 0; i < 4; i++) {
            int idx = tid + i * 256;
            int row = idx >> 3, seg = idx & 7;
            cp16(As[s] + row * KS + seg * 8, Ag + (size_t)row * 1536 + seg * 8);
            cp16(Ws[s] + row * KS + seg * 8, Wg + (size_t)row * 1536 + seg * 8);
        }
        asm volatile("cp.async.commit_group;");
    };

    load_stage(0, 0);

    for (int kc = 0; kc < 24; ++kc) {
        const int s = kc & 1;
        if (kc + 1 < 24) load_stage(s ^ 1, kc + 1);
        if (kc + 1 < 24) asm volatile("cp.async.wait_group 1;" ::: "memory");
        else             asm volatile("cp.async.wait_group 0;" ::: "memory");
        __syncthreads();

        const __nv_bfloat16* Ab = As[s] + (wm * 64 + gid) * KS + tig * 2;
        const __nv_bfloat16* Wb2 = Ws[s] + (wn * 32 + gid) * KS + tig * 2;

#pragma unroll
        for (int kk = 0; kk < 4; ++kk) {
            const int k0 = kk * 16;
            uint32_t a[4][4];
#pragma unroll
            for (int mt = 0; mt < 4; mt++) {
                const __nv_bfloat16* p = Ab + mt * 16 * KS + k0;
                a[mt][0] = *(const uint32_t*)(p);
                a[mt][1] = *(const uint32_t*)(p + 8 * KS);
                a[mt][2] = *(const uint32_t*)(p + 8);
                a[mt][3] = *(const uint32_t*)(p + 8 * KS + 8);
            }
            uint32_t bf[4][2];
#pragma unroll
            for (int nt = 0; nt < 4; nt++) {
                const __nv_bfloat16* p = Wb2 + nt * 8 * KS + k0;
                bf[nt][0] = *(const uint32_t*)(p);
                bf[nt][1] = *(const uint32_t*)(p + 8);
            }
#pragma unroll
            for (int mt = 0; mt < 4; mt++)
#pragma unroll
                for (int nt = 0; nt < 4; nt++)
                    mma_bf16(acc[mt][nt][0], acc[mt][nt][1],
                             acc[mt][nt][2], acc[mt][nt][3],
                             a[mt][0], a[mt][1], a[mt][2], a[mt][3],
                             bf[nt][0], bf[nt][1]);
        }
        __syncthreads();
    }

#pragma unroll
    for (int mt = 0; mt < 4; mt++) {
        int mrow = m0 + wm * 64 + mt * 16 + gid;
#pragma unroll
        for (int nt = 0; nt < 4; nt++) {
            int ncol = n0 + wn * 32 + nt * 8 + tig * 2;
            float* d0 = G_buf + (size_t)mrow * 2048 + ncol;
            float* d1 = G_buf + (size_t)(mrow + 8) * 2048 + ncol;
            *(float2*)d0 = make_float2(acc[mt][nt][0], acc[mt][nt][1]);
            *(float2*)d1 = make_float2(acc[mt][nt][2], acc[mt][nt][3]);
        }
    }
}

// ---------------------------------------------------------------------------
// Transpose G[b*1024+t][j] -> Gt[t][j][b], adding bias per j. (proven)
// ---------------------------------------------------------------------------
__global__ void __launch_bounds__(256) transp(
    const float* __restrict__ bif, const float* __restrict__ bhf,
    const float* __restrict__ bib, const float* __restrict__ bhb) {
    __shared__ float tile[64][65];
    const int t  = blockIdx.y;
    const int j0 = blockIdx.x * 64;
    const int tid = threadIdx.x;

    const int jq = (tid & 15) * 4;
    const int bb = tid >> 4;
#pragma unroll
    for (int p = 0; p < 4; p++) {
        int bi = bb + p * 16;
        float4 v = *(const float4*)(G_buf + ((size_t)(bi * 1024 + t)) * 2048 + j0 + jq);
        tile[bi][jq + 0] = v.x; tile[bi][jq + 1] = v.y;
        tile[bi][jq + 2] = v.z; tile[bi][jq + 3] = v.w;
    }
    __syncthreads();

    const int bq = (tid & 15) * 4;
    const int jj = tid >> 4;
#pragma unroll
    for (int p = 0; p < 4; p++) {
        int j = jj + p * 16;
        int jg = j0 + j;
        float bias = (jg < 1024) ? (bif[jg] + bhf[jg])
                                 : (bib[jg - 1024] + bhb[jg - 1024]);
        float4 v = make_float4(tile[bq + 0][j] + bias, tile[bq + 1][j] + bias,
                               tile[bq + 2][j] + bias, tile[bq + 3][j] + bias);
        *(float4*)(Gt_buf + ((size_t)t * 2048 + j0 + j) * 64 + bq) = v;
    }
}

// ---------------------------------------------------------------------------
// Phase 2: persistent recurrence with tensor-core inner product.
// CTA = (dir, bg 0..3, qs 0..15): q in [qs*16,+16) x b in [bg*16,+16).
// gates[16b x 64g] = hsplit[16b x 768k'] @ Wsplit[768k' x 64g] via m16n8k16.
// Weights (hi/lo split) live in registers: warp w holds chunks {w+8j}, j=0..5,
// 8 n-tiles each (96 regs). h staged from Hhist and hi/lo split into smem
// (pitch 520 bf16 -> conflict-free A-frag LDS). 8-warp partial reduction in
// smem; warp w finalizes n-tile w; shfl_xor(1) pairs (i,f)/(g,o) lanes.
// Sync skeleton identical to R9/R15.
// ---------------------------------------------------------------------------
__global__ void __launch_bounds__(256, 1) recur(
    const float* __restrict__ Whf, const float* __restrict__ Whb)
{
    extern __shared__ __align__(16) char smr[];
    __nv_bfloat16* hA = (__nv_bfloat16*)smr;        // [16 b][520] (hi 0..255, lo 256..511)
    float* red = (float*)(smr + 16640);             // [8 srcwarp][8 nt][32 lane][4]

    const int cta = blockIdx.x;
    const int dir = cta >> 6;
    const int grp = cta & 63;
    const int bg  = grp >> 4;
    const int qs  = grp & 15;
    const int b0  = bg * 16;
    const int qb  = qs * 16;
    const int tid = threadIdx.x;
    const int wid = tid >> 5;
    const int lane = tid & 31;
    const int gid = lane >> 2;
    const int tig = lane & 3;

    const float* W = dir ? Whb : Whf;

    // ---- B fragments in registers (one-time) ----
    uint32_t breg[6][8][2];
#pragma unroll
    for (int j = 0; j < 6; j++) {
        int c = wid + 8 * j;            // chunk 0..47
        int s = c >> 4;                 // section: 0 hi*Whi, 1 hi*Wlo, 2 lo*Whi
        int k16 = (c & 15) << 4;
        bool useLo = (s == 1);
#pragma unroll
        for (int nt = 0; nt < 8; nt++) {
            int n = nt * 8 + gid;
            int qloc = n >> 2, g = n & 3;
            const float* wr = W + (size_t)(g * 256 + qb + qloc) * 256 + k16 + 2 * tig;
            float w0 = __ldg(wr), w1 = __ldg(wr + 1);
            float w2 = __ldg(wr + 8), w3 = __ldg(wr + 9);
            __nv_bfloat16 h0 = __float2bfloat16(w0), h1 = __float2bfloat16(w1);
            __nv_bfloat16 h2 = __float2bfloat16(w2), h3 = __float2bfloat16(w3);
            if (useLo) {
                h0 = __float2bfloat16(w0 - __bfloat162float(h0));
                h1 = __float2bfloat16(w1 - __bfloat162float(h1));
                h2 = __float2bfloat16(w2 - __bfloat162float(h2));
                h3 = __float2bfloat16(w3 - __bfloat162float(h3));
            }
            breg[j][nt][0] = pkbf(h0, h1);
            breg[j][nt][1] = pkbf(h2, h3);
        }
    }

    // This thread's gate columns (within final n-tile wid)
    const int n_my = 8 * wid + 2 * tig;
    const int qlm  = n_my >> 2;         // local q (0..15)
    const int g0   = n_my & 3;          // 0 or 2

    float cst0 = 0.f, cst1 = 0.f;
    int t = dir ? 1023 : 0;

    float pre[4];
    {
        const float* base = Gt_buf + ((size_t)t * 2048 + (size_t)dir * 1024) * 64;
        const float* p0 = base + (size_t)(g0 * 256 + qb + qlm) * 64 + b0 + gid;
        const float* p1 = base + (size_t)((g0 + 1) * 256 + qb + qlm) * 64 + b0 + gid;
        pre[0] = __ldg(p0);     pre[1] = __ldg(p1);
        pre[2] = __ldg(p0 + 8); pre[3] = __ldg(p1 + 8);
    }

    float* Hd = Hhist + (size_t)dir * 1024 * 16384;

    for (int step = 0; step < 1024; ++step) {
        // ---- stage h: Hhist fp32 -> hi/lo bf16 split in hA ----
        if (step == 0) {
            uint32_t* z = (uint32_t*)hA;
            for (int i = tid; i < 4160; i += 256) z[i] = 0u;
        } else {
            const int tp = dir ? (t + 1) : (t - 1);
            const float* src = Hd + (size_t)tp * 16384 + (size_t)tid * 64 + b0;
            float4 v0 = __ldcg((const float4*)src);
            float4 v1 = __ldcg((const float4*)(src + 4));
            float4 v2 = __ldcg((const float4*)(src + 8));
            float4 v3 = __ldcg((const float4*)(src + 12));
            float vv[16] = {v0.x, v0.y, v0.z, v0.w, v1.x, v1.y, v1.z, v1.w,
                            v2.x, v2.y, v2.z, v2.w, v3.x, v3.y, v3.z, v3.w};
#pragma unroll
            for (int bb = 0; bb < 16; bb++) {
                float val = vv[bb];
                __nv_bfloat16 hi = __float2bfloat16(val);
                __nv_bfloat16 lo = __float2bfloat16(val - __bfloat162float(hi));
                hA[bb * 520 + tid] = hi;
                hA[bb * 520 + 256 + tid] = lo;
            }
        }
        __syncthreads();

        // ---- tensor-core gates ----
        float acc[8][4];
#pragma unroll
        for (int nt = 0; nt < 8; nt++)
#pragma unroll
            for (int k = 0; k < 4; k++) acc[nt][k] = 0.f;

#pragma unroll
        for (int j = 0; j < 6; j++) {
            int c = wid + 8 * j;
            int koff = ((c >> 4) == 2 ? 256 : 0) + ((c & 15) << 4);
            const __nv_bfloat16* pa = hA + gid * 520 + koff + 2 * tig;
            uint32_t a0 = *(const uint32_t*)(pa);
            uint32_t a1 = *(const uint32_t*)(pa + 8 * 520);
            uint32_t a2 = *(const uint32_t*)(pa + 8);
            uint32_t a3 = *(const uint32_t*)(pa + 8 * 520 + 8);
#pragma unroll
            for (int nt = 0; nt < 8; nt++)
                mma_bf16(acc[nt][0], acc[nt][1], acc[nt][2], acc[nt][3],
                         a0, a1, a2, a3, breg[j][nt][0], breg[j][nt][1]);
        }

        // ---- cross-warp reduction ----
#pragma unroll
        for (int nt = 0; nt < 8; nt++)
            *(float4*)(red + ((size_t)(wid * 8 + nt) * 32 + lane) * 4) =
                make_float4(acc[nt][0], acc[nt][1], acc[nt][2], acc[nt][3]);
        __syncthreads();

        float r0 = pre[0], r1 = pre[1], r2 = pre[2], r3 = pre[3];
#pragma unroll
        for (int sw = 0; sw < 8; sw++) {
            float4 v = *(const float4*)(red + ((size_t)(sw * 8 + wid) * 32 + lane) * 4);
            r0 += v.x; r1 += v.y; r2 += v.z; r3 += v.w;
        }

        // exchange (i,f) <-> (g,o) between paired lanes
        float o0 = __shfl_xor_sync(0xffffffffu, r0, 1);
        float o1 = __shfl_xor_sync(0xffffffffu, r1, 1);
        float o2 = __shfl_xor_sync(0xffffffffu, r2, 1);
        float o3 = __shfl_xor_sync(0xffffffffu, r3, 1);

        if ((tig & 1) == 0) {
            float ig = sigm_f(r0), fg = sigm_f(r1);
            float gg = tanh_f(o0), og = sigm_f(o1);
            cst0 = fg * cst0 + ig * gg;
            float h0v = og * tanh_f(cst0);
            ig = sigm_f(r2); fg = sigm_f(r3);
            gg = tanh_f(o2); og = sigm_f(o3);
            cst1 = fg * cst1 + ig * gg;
            float h1v = og * tanh_f(cst1);
            float* hd = Hd + (size_t)t * 16384 + (size_t)(qb + qlm) * 64 + b0 + gid;
            __stcg(hd, h0v);
            __stcg(hd + 8, h1v);
        }

        if (step == 1023) break;

        // ---- arrive ----
        __threadfence();
        __syncthreads();
        if (tid == 0) st_rel(&g_arrive[dir][bg][qs][0], (unsigned)(step + 1));

        // prefetch next step's gates under the wait
        t = dir ? (1022 - step) : (step + 1);
        {
            const float* base = Gt_buf + ((size_t)t * 2048 + (size_t)dir * 1024) * 64;
            const float* p0 = base + (size_t)(g0 * 256 + qb + qlm) * 64 + b0 + gid;
            const float* p1 = base + (size_t)((g0 + 1) * 256 + qb + qlm) * 64 + b0 + gid;
            pre[0] = __ldg(p0);     pre[1] = __ldg(p1);
            pre[2] = __ldg(p0 + 8); pre[3] = __ldg(p1 + 8);
        }

        // ---- wait: warp-2 lanes 0..15 poll the group's 16 flags ----
        if (tid >= 64 && tid < 80) {
            while (ld_acq(&g_arrive[dir][bg][tid - 64][0]) <= (unsigned)step) {}
        }
        __syncthreads();
    }
}

// ---------------------------------------------------------------------------
// Final: out[b][t][dir*256+q] = Hhist[dir][t][q*64+b]
// ---------------------------------------------------------------------------
__global__ void __launch_bounds__(256) out_tr(float* __restrict__ out) {
    __shared__ float tile[64][65];
    const int q0  = blockIdx.x * 64;
    const int t   = blockIdx.y;
    const int dir = blockIdx.z;
    const int tid = threadIdx.x;

    const float* src = Hhist + ((size_t)dir * 1024 + t) * 16384;
    const int b  = tid & 63;
    const int q4 = (tid >> 6) * 16;
#pragma unroll
    for (int i = 0; i < 16; i++) {
        int qq = q4 + i;
        tile[b][qq] = src[(q0 + qq) * 64 + b];
    }
    __syncthreads();

    const int qs = (tid & 15) * 4;
    const int br = tid >> 4;
#pragma unroll
    for (int p = 0; p < 4; p++) {
        int bb = br + p * 16;
        float4 v = make_float4(tile[bb][qs + 0], tile[bb][qs + 1],
                               tile[bb][qs + 2], tile[bb][qs + 3]);
        *(float4*)(out + ((size_t)bb * 1024 + t) * 512 + dir * 256 + q0 + qs) = v;
    }
}

// ---------------------------------------------------------------------------
extern "C" void kernel_launch(void* const* d_in, const int* in_sizes, int n_in,
                              void* d_out, int out_size) {
    const float* x   = (const float*)d_in[0];
    const float* Wif = (const float*)d_in[1];
    const float* Whf = (const float*)d_in[2];
    const float* bif = (const float*)d_in[3];
    const float* bhf = (const float*)d_in[4];
    const float* Wib = (const float*)d_in[5];
    const float* Whb = (const float*)d_in[6];
    const float* bib = (const float*)d_in[7];
    const float* bhb = (const float*)d_in[8];
    float* out = (float*)d_out;

    // recur smem: hA 16640 + red 32768 = 49408 (+pad)
    cudaFuncSetAttribute(recur,    cudaFuncAttributeMaxDynamicSharedMemorySize, 49536);
    cudaFuncSetAttribute(gemm_mma, cudaFuncAttributeMaxDynamicSharedMemorySize, 73728);

    reset_k<<<16, 256>>>();
    convA<<<65536, 256>>>(x);
    convW<<<2048, 256>>>(Wif, Wib);
    gemm_mma<<<dim3(16, 512), 256, 73728>>>();
    transp<<<dim3(32, 1024), 256>>>(bif, bhf, bib, bhb);
    recur<<<128, 256, 49536>>>(Whf, Whb);
    out_tr<<<dim3(4, 1024, 2), 256>>>(out);
}